// round 5
// baseline (speedup 1.0000x reference)
#include <cuda_runtime.h>
#include <cuda_fp16.h>
#include <cstdint>

#define NPIX 9216
#define HH 96
#define CC 21
#define NB 24
#define CRF_ITERS 5
#define APP_W 10.0f
#define SMO_W 3.0f

#define NBLK 144                 // 64-pixel blocks
#define NSTEP 72                 // J-steps per CTA (split-K over 2 halves)

// GEMM smem stage layout (row pitch 144 B = 72 halves; 16B phase shift/row)
#define PITCH 144
#define AHI 0
#define ALO (64 * PITCH)                 // 9216
#define PHI (2 * 64 * PITCH)             // 18432
#define PLO (PHI + NB * PITCH)           // 21888
#define STAGEB (PLO + NB * PITCH)        // 25344
#define NSTAGE 3
#define GEMM_SMEM (NSTAGE * STAGEB)      // 76032
#define FULLB ((128 + 48) * 128)         // 22528 bytes per stage

// ---------------- persistent device scratch ----------------
static __device__ __half g_Khi[(size_t)NPIX * NPIX];   // upper-tri 64-blocks only
static __device__ __half g_Klo[(size_t)NPIX * NPIX];
static __device__ float  g_feat[6 * NPIX];
static __device__ float  g_gauss[HH];
static __device__ float  g_unary[CC * NPIX];
static __device__ __half g_Bhi[NB * NPIX];
static __device__ __half g_Blo[NB * NPIX];
static __device__ float  g_part[2][(size_t)NPIX * NB]; // split-K partials
static __device__ float  g_tmp[CC * NPIX];
static __device__ float  g_smo[CC * NPIX];

// ---------------- PTX helpers ----------------
__device__ __forceinline__ uint32_t smem_u32(const void* p) {
    uint32_t a;
    asm("{ .reg .u64 t; cvta.to.shared.u64 t, %1; cvt.u32.u64 %0, t; }" : "=r"(a) : "l"(p));
    return a;
}
__device__ __forceinline__ void mbar_init(uint32_t a, uint32_t c) {
    asm volatile("mbarrier.init.shared.b64 [%0], %1;" :: "r"(a), "r"(c) : "memory");
}
__device__ __forceinline__ void mbar_expect_tx(uint32_t a, uint32_t bytes) {
    asm volatile("mbarrier.arrive.expect_tx.shared.b64 _, [%0], %1;" :: "r"(a), "r"(bytes) : "memory");
}
__device__ __forceinline__ void mbar_wait(uint32_t mbar, uint32_t parity) {
    asm volatile(
        "{\n\t.reg .pred P1;\n\t"
        "WL%=:\n\t"
        "mbarrier.try_wait.parity.shared.b64 P1, [%0], %1;\n\t"
        "@!P1 bra WL%=;\n\t}"
        :: "r"(mbar), "r"(parity) : "memory");
}
__device__ __forceinline__ void bulk_cp(uint32_t dst, const void* src, uint32_t bytes, uint32_t mbar) {
    asm volatile(
        "cp.async.bulk.shared::cluster.global.mbarrier::complete_tx::bytes [%0], [%1], %2, [%3];"
        :: "r"(dst), "l"(src), "r"(bytes), "r"(mbar) : "memory");
}
__device__ __forceinline__ void ldsm4(uint32_t& r0, uint32_t& r1, uint32_t& r2, uint32_t& r3, uint32_t addr) {
    asm volatile("ldmatrix.sync.aligned.m8n8.x4.shared.b16 {%0,%1,%2,%3}, [%4];"
        : "=r"(r0), "=r"(r1), "=r"(r2), "=r"(r3) : "r"(addr));
}
__device__ __forceinline__ void ldsm4t(uint32_t& r0, uint32_t& r1, uint32_t& r2, uint32_t& r3, uint32_t addr) {
    asm volatile("ldmatrix.sync.aligned.m8n8.x4.trans.shared.b16 {%0,%1,%2,%3}, [%4];"
        : "=r"(r0), "=r"(r1), "=r"(r2), "=r"(r3) : "r"(addr));
}
__device__ __forceinline__ void ldsm2(uint32_t& r0, uint32_t& r1, uint32_t addr) {
    asm volatile("ldmatrix.sync.aligned.m8n8.x2.shared.b16 {%0,%1}, [%2];"
        : "=r"(r0), "=r"(r1) : "r"(addr));
}
__device__ __forceinline__ void hmma(float* c, const uint32_t* a, const uint32_t* b) {
    asm volatile(
        "mma.sync.aligned.m16n8k16.row.col.f32.f16.f16.f32 "
        "{%0,%1,%2,%3}, {%4,%5,%6,%7}, {%8,%9}, {%0,%1,%2,%3};"
        : "+f"(c[0]), "+f"(c[1]), "+f"(c[2]), "+f"(c[3])
        : "r"(a[0]), "r"(a[1]), "r"(a[2]), "r"(a[3]), "r"(b[0]), "r"(b[1]));
}
__device__ __forceinline__ void tri_decode(int bid, int& lo, int& hi) {
    int r = (int)((sqrtf(8.0f * (float)bid + 1.0f) - 1.0f) * 0.5f);
    while ((r + 1) * (r + 2) / 2 <= bid) ++r;
    while (r * (r + 1) / 2 > bid) --r;
    hi = r;
    lo = bid - r * (r + 1) / 2;
}

// ---------------- kernels ----------------

__global__ void k_feat(const float* __restrict__ x) {
    int n = blockIdx.x * blockDim.x + threadIdx.x;
    if (n >= NPIX) return;
    int y = n / HH, xc = n % HH;
    float f0 = (float)y  * (1.0f / 30.0f);
    float f1 = (float)xc * (1.0f / 30.0f);
    float f2 = x[n]            * 10.0f;
    float f3 = x[NPIX + n]     * 10.0f;
    float f4 = x[2 * NPIX + n] * 10.0f;
    float sq = f0*f0 + f1*f1 + f2*f2 + f3*f3 + f4*f4;
    g_feat[n]            = sq;
    g_feat[NPIX     + n] = f0;
    g_feat[2*NPIX   + n] = f1;
    g_feat[3*NPIX   + n] = f2;
    g_feat[4*NPIX   + n] = f3;
    g_feat[5*NPIX   + n] = f4;
    if (n < HH) g_gauss[n] = expf(-(float)(n * n) * (1.0f / 18.0f));
}

// Upper-triangle-only build: 64x64 tiles (ta <= tb). No mirror writes.
__global__ void __launch_bounds__(256) k_build_ut() {
    int ta, tb;
    tri_decode(blockIdx.x, ta, tb);
    int tid = threadIdx.x;
    int r  = tid >> 2;
    int bq = (tid & 3) * 16;

    int a = ta * 64 + r;
    float sqa = g_feat[a];
    float a0 = g_feat[NPIX   + a];
    float a1 = g_feat[2*NPIX + a];
    float a2 = g_feat[3*NPIX + a];
    float a3 = g_feat[4*NPIX + a];
    float a4 = g_feat[5*NPIX + a];

    #pragma unroll
    for (int q = 0; q < 8; ++q) {
        int b = tb * 64 + bq + 2 * q;
        float2 sqb = *(const float2*)&g_feat[b];
        float2 b0  = *(const float2*)&g_feat[NPIX   + b];
        float2 b1  = *(const float2*)&g_feat[2*NPIX + b];
        float2 b2  = *(const float2*)&g_feat[3*NPIX + b];
        float2 b3  = *(const float2*)&g_feat[4*NPIX + b];
        float2 b4  = *(const float2*)&g_feat[5*NPIX + b];
        float dotx = a0*b0.x + a1*b1.x + a2*b2.x + a3*b3.x + a4*b4.x;
        float doty = a0*b0.y + a1*b1.y + a2*b2.y + a3*b3.y + a4*b4.y;
        float kx = APP_W * __expf(-0.5f * fmaxf(sqa + sqb.x - 2.0f * dotx, 0.0f));
        float ky = APP_W * __expf(-0.5f * fmaxf(sqa + sqb.y - 2.0f * doty, 0.0f));
        __half hx = __float2half_rn(kx);
        __half hy = __float2half_rn(ky);
        __half lx = __float2half_rn(kx - __half2float(hx));
        __half ly = __float2half_rn(ky - __half2float(hy));
        size_t idx = (size_t)a * NPIX + b;
        *(__half2*)&g_Khi[idx] = __halves2half2(hx, hy);
        *(__half2*)&g_Klo[idx] = __halves2half2(lx, ly);
    }
}

__device__ __forceinline__ void write_probs(int n, const float* u, float inv, float* out_cm) {
    #pragma unroll
    for (int c = 0; c < CC; c++) {
        float o = u[c] * inv;
        out_cm[c * NPIX + n] = o;
        __half h = __float2half_rn(o);
        g_Bhi[c * NPIX + n] = h;
        g_Blo[c * NPIX + n] = __float2half_rn(o - __half2float(h));
    }
}

__global__ void k_init(const float* __restrict__ yhat, float* __restrict__ out_cm) {
    int n = blockIdx.x * blockDim.x + threadIdx.x;
    if (n >= NPIX) return;
    float u[CC];
    float mx = -1e30f;
    #pragma unroll
    for (int c = 0; c < CC; c++) {
        float v = yhat[c * NPIX + n];
        g_unary[c * NPIX + n] = v;
        u[c] = v;
        mx = fmaxf(mx, v);
    }
    float s = 0.0f;
    #pragma unroll
    for (int c = 0; c < CC; c++) { u[c] = __expf(u[c] - mx); s += u[c]; }
    write_probs(n, u, 1.0f / s, out_cm);
    #pragma unroll
    for (int c = CC; c < NB; c++) {
        g_Bhi[c * NPIX + n] = __float2half_rn(0.0f);
        g_Blo[c * NPIX + n] = __float2half_rn(0.0f);
    }
}

// Fill one pipeline stage: stored K-tile (min(I,J), max(I,J)) + P block J.
__device__ __forceinline__ void fill_stage(uint32_t st, int I, int J, uint32_t mb, int tid) {
    if (tid < 128) {
        int plane = tid >> 6, row = tid & 63;
        int lo = (I < J) ? I : J;
        int hi = (I < J) ? J : I;
        const __half* src = (plane ? g_Klo : g_Khi) + (size_t)(lo * 64 + row) * NPIX + hi * 64;
        bulk_cp(st + (plane ? ALO : AHI) + row * PITCH, src, 128, mb);
    } else if (tid < 176) {
        int i = tid - 128;
        int plane = i / NB, c = i % NB;
        const __half* src = (plane ? g_Blo : g_Bhi) + (size_t)c * NPIX + J * 64;
        bulk_cp(st + (plane ? PLO : PHI) + c * PITCH, src, 128, mb);
    }
}

// Owner-computes symmetric GEMM: CTA (I, h) accumulates out block I over its 72
// J-steps in registers; J = (72h + t - I) mod 144 pairs both readers of a stored
// tile at the same step (L2 hit for the second). No atomics.
__global__ void __launch_bounds__(256, 2) k_gemm_sym2() {
    extern __shared__ char smem[];
    __shared__ uint64_t mbar_s[NSTAGE];
    uint32_t sb = smem_u32(smem);
    int tid = threadIdx.x;
    int lane = tid & 31;
    int w = tid >> 5;
    int r = w & 3;          // row group (16 rows)
    int kh = w >> 2;        // k-half (0: k 0-31, 1: k 32-63)
    int I = blockIdx.x;
    int h = blockIdx.y;

    uint32_t mb[NSTAGE];
    #pragma unroll
    for (int s = 0; s < NSTAGE; s++) mb[s] = smem_u32(&mbar_s[s]);
    if (tid < NSTAGE) mbar_init(mb[tid], 1);
    __syncthreads();
    if (tid == 0) {
        #pragma unroll
        for (int s = 0; s < NSTAGE; s++) mbar_expect_tx(mb[s], FULLB);
    }
    __syncthreads();
    #pragma unroll
    for (int s = 0; s < NSTAGE; s++) {
        int J = (72 * h + s - I + 144) % 144;
        fill_stage(sb + s * STAGEB, I, J, mb[s], tid);
    }

    // straight A frag addr: row = r*16 + (lane&15), col bytes = (lane>>4)*16 + kh*64 (+ks*32)
    uint32_t a_off = (uint32_t)((r * 16 + (lane & 15)) * PITCH + (lane >> 4) * 16 + kh * 64);
    // transposed A frag addr (stored tile is (J,I)): row = k, col = m
    int gg = lane >> 3;
    uint32_t t_off = (uint32_t)((kh * 32 + (gg >> 1) * 8 + (lane & 7)) * PITCH
                                + (r * 16 + (gg & 1) * 8) * 2);
    // B frag addr: row = class, col = k
    int l2 = lane & 15;
    uint32_t b_off = (uint32_t)(((l2 & 7)) * PITCH + ((l2 >> 3) & 1) * 16 + kh * 64);

    float acc[3][3][4];
    #pragma unroll
    for (int tm = 0; tm < 3; tm++)
        #pragma unroll
        for (int nt = 0; nt < 3; nt++)
            #pragma unroll
            for (int q = 0; q < 4; q++) acc[tm][nt][q] = 0.0f;

    for (int t = 0; t < NSTEP; ++t) {
        int s = t % NSTAGE;
        uint32_t st = sb + s * STAGEB;
        mbar_wait(mb[s], (t / NSTAGE) & 1);
        int J = (72 * h + t - I + 144) % 144;

        if (J >= I) {
            #pragma unroll
            for (int ks = 0; ks < 2; ++ks) {
                uint32_t ah[4], al[4];
                ldsm4(ah[0], ah[1], ah[2], ah[3], st + AHI + a_off + ks * 32);
                ldsm4(al[0], al[1], al[2], al[3], st + ALO + a_off + ks * 32);
                #pragma unroll
                for (int nt = 0; nt < 3; ++nt) {
                    uint32_t bh[2], bl[2];
                    ldsm2(bh[0], bh[1], st + PHI + nt * 8 * PITCH + b_off + ks * 32);
                    ldsm2(bl[0], bl[1], st + PLO + nt * 8 * PITCH + b_off + ks * 32);
                    hmma(acc[0][nt], ah, bh);
                    hmma(acc[1][nt], ah, bl);
                    hmma(acc[2][nt], al, bh);
                }
            }
        } else {
            #pragma unroll
            for (int ks = 0; ks < 2; ++ks) {
                uint32_t ah[4], al[4];
                ldsm4t(ah[0], ah[1], ah[2], ah[3], st + AHI + t_off + ks * 16 * PITCH);
                ldsm4t(al[0], al[1], al[2], al[3], st + ALO + t_off + ks * 16 * PITCH);
                #pragma unroll
                for (int nt = 0; nt < 3; ++nt) {
                    uint32_t bh[2], bl[2];
                    ldsm2(bh[0], bh[1], st + PHI + nt * 8 * PITCH + b_off + ks * 32);
                    ldsm2(bl[0], bl[1], st + PLO + nt * 8 * PITCH + b_off + ks * 32);
                    hmma(acc[0][nt], ah, bh);
                    hmma(acc[1][nt], ah, bl);
                    hmma(acc[2][nt], al, bh);
                }
            }
        }
        __syncthreads();
        if (t + NSTAGE < NSTEP) {
            if (tid == 0) mbar_expect_tx(mb[s], FULLB);
            __syncthreads();
            int Jn = (72 * h + t + NSTAGE - I + 144) % 144;
            fill_stage(st, I, Jn, mb[s], tid);
        }
    }

    // epilogue: sum 3 terms, reduce k-halves through smem, single STG to g_part[h]
    float sum_[3][4];
    #pragma unroll
    for (int nt = 0; nt < 3; nt++)
        #pragma unroll
        for (int q = 0; q < 4; q++)
            sum_[nt][q] = acc[0][nt][q] + acc[1][nt][q] + acc[2][nt][q];

    float* red = (float*)smem;              // 64 x 26 floats, aliases stage mem
    int row16 = lane >> 2;
    int cb = (lane & 3) * 2;
    if (kh == 1) {
        #pragma unroll
        for (int nt = 0; nt < 3; ++nt) {
            red[(r * 16 + row16) * 26 + nt * 8 + cb]           = sum_[nt][0];
            red[(r * 16 + row16) * 26 + nt * 8 + cb + 1]       = sum_[nt][1];
            red[(r * 16 + row16 + 8) * 26 + nt * 8 + cb]       = sum_[nt][2];
            red[(r * 16 + row16 + 8) * 26 + nt * 8 + cb + 1]   = sum_[nt][3];
        }
    }
    __syncthreads();
    if (kh == 0) {
        float* dst = g_part[h];
        int rg0 = I * 64 + r * 16 + row16;
        #pragma unroll
        for (int nt = 0; nt < 3; ++nt) {
            float s0 = sum_[nt][0] + red[(r * 16 + row16) * 26 + nt * 8 + cb];
            float s1 = sum_[nt][1] + red[(r * 16 + row16) * 26 + nt * 8 + cb + 1];
            float s2 = sum_[nt][2] + red[(r * 16 + row16 + 8) * 26 + nt * 8 + cb];
            float s3 = sum_[nt][3] + red[(r * 16 + row16 + 8) * 26 + nt * 8 + cb + 1];
            *(float2*)&dst[(size_t)rg0 * NB + nt * 8 + cb]       = make_float2(s0, s1);
            *(float2*)&dst[(size_t)(rg0 + 8) * NB + nt * 8 + cb] = make_float2(s2, s3);
        }
    }
}

// Separable smoothness: horizontal pass.
__global__ void k_convx(const float* __restrict__ out_cm) {
    __shared__ float sg[HH];
    if (threadIdx.x < HH) sg[threadIdx.x] = g_gauss[threadIdx.x];
    __syncthreads();
    int idx = blockIdx.x * blockDim.x + threadIdx.x;
    if (idx >= CC * NPIX) return;
    int xp = idx % HH;
    const float* row = out_cm + (idx - xp);
    float s = 0.0f;
    #pragma unroll 8
    for (int xx = 0; xx < HH; ++xx) {
        int d = xx - xp; d = (d < 0) ? -d : d;
        s += row[xx] * sg[d];
    }
    g_tmp[idx] = s;
}

// Separable smoothness: vertical pass.
__global__ void k_convy() {
    __shared__ float sg[HH];
    if (threadIdx.x < HH) sg[threadIdx.x] = g_gauss[threadIdx.x];
    __syncthreads();
    int idx = blockIdx.x * blockDim.x + threadIdx.x;
    if (idx >= CC * NPIX) return;
    int xp = idx % HH;
    int yp = (idx / HH) % HH;
    int c  = idx / NPIX;
    const float* col = g_tmp + c * NPIX + xp;
    float s = 0.0f;
    #pragma unroll 8
    for (int y = 0; y < HH; ++y) {
        int d = y - yp; d = (d < 0) ? -d : d;
        s += col[y * HH] * sg[d];
    }
    g_smo[idx] = s;
}

__global__ void k_combine(const float* __restrict__ mu, float* __restrict__ out_cm) {
    __shared__ float smu[CC * CC];
    for (int i = threadIdx.x; i < CC * CC; i += blockDim.x) smu[i] = mu[i];
    __syncthreads();
    int n = blockIdx.x * blockDim.x + threadIdx.x;
    if (n >= NPIX) return;
    float m[CC];
    #pragma unroll
    for (int c = 0; c < CC; c++)
        m[c] = g_part[0][(size_t)n * NB + c] + g_part[1][(size_t)n * NB + c]
             + SMO_W * g_smo[c * NPIX + n];
    float u[CC];
    float mx = -1e30f;
    #pragma unroll
    for (int c = 0; c < CC; c++) {
        float s = 0.0f;
        #pragma unroll
        for (int c2 = 0; c2 < CC; c2++) s = fmaf(smu[c2 * CC + c], m[c2], s);
        float v = g_unary[c * NPIX + n] + s;
        g_unary[c * NPIX + n] = v;
        u[c] = v;
        mx = fmaxf(mx, v);
    }
    float s = 0.0f;
    #pragma unroll
    for (int c = 0; c < CC; c++) { u[c] = __expf(u[c] - mx); s += u[c]; }
    write_probs(n, u, 1.0f / s, out_cm);
}

// ---------------- launch ----------------
extern "C" void kernel_launch(void* const* d_in, const int* in_sizes, int n_in,
                              void* d_out, int out_size) {
    const float* x    = (const float*)d_in[0];
    const float* yhat = (const float*)d_in[1];
    const float* mu   = (const float*)d_in[2];
    float* out = (float*)d_out;

    cudaFuncSetAttribute(k_gemm_sym2, cudaFuncAttributeMaxDynamicSharedMemorySize, GEMM_SMEM);

    k_feat<<<(NPIX + 255) / 256, 256>>>(x);
    k_build_ut<<<NBLK * (NBLK + 1) / 2, 256>>>();
    k_init<<<(NPIX + 255) / 256, 256>>>(yhat, out);

    for (int it = 0; it < CRF_ITERS; ++it) {
        k_gemm_sym2<<<dim3(NBLK, 2), 256, GEMM_SMEM>>>();
        k_convx<<<(CC * NPIX + 127) / 128, 128>>>(out);
        k_convy<<<(CC * NPIX + 127) / 128, 128>>>();
        k_combine<<<(NPIX + 127) / 128, 128>>>(mu, out);
    }
}

// round 6
// speedup vs baseline: 1.6383x; 1.6383x over previous
#include <cuda_runtime.h>
#include <cuda_fp16.h>
#include <cstdint>

#define NPIX 9216
#define HH 96
#define CC 21
#define NB 24
#define CRF_ITERS 5
#define APP_W 10.0f
#define SMO_W 3.0f

#define NBLK 144                  // 64-pixel blocks
#define NTILE (NBLK * (NBLK + 1) / 2)   // 10440 stored upper-tri tiles
#define NSTEP 36                  // steps per CTA (2 J-blocks per step, split-K x2)

// smem stage layout (bytes): 2 A-tiles (hi+lo) + 2 P-tiles (hi+lo)
#define A0HI 0
#define A0LO 8192
#define A1HI 16384
#define A1LO 24576
#define P0HI 32768
#define P0LO 35840
#define P1HI 38912
#define P1LO 41984
#define STAGEB 45056
#define NSTAGE 2
#define GEMM_SMEM (NSTAGE * STAGEB)   // 90112
#define FULLB 45056

// XOR swizzle baked into gmem tile layout: flips 16B-chunk bits with row&7
#define SW(off) ((off) ^ ((((off) >> 7) & 7) << 4))

// ---------------- persistent device scratch ----------------
static __device__ __half g_Khi[(size_t)NTILE * 4096];  // 85.5 MB, tile-contiguous
static __device__ __half g_Klo[(size_t)NTILE * 4096];
static __device__ float  g_feat[6 * NPIX];
static __device__ float  g_gauss[HH];
static __device__ float  g_unary[CC * NPIX];
static __device__ __half g_Bhi[NBLK * NB * 64];        // [block][class][64], swizzled
static __device__ __half g_Blo[NBLK * NB * 64];
static __device__ float  g_part[2][(size_t)NPIX * NB];
static __device__ float  g_tmp[CC * NPIX];
static __device__ float  g_smo[CC * NPIX];

// ---------------- PTX helpers ----------------
__device__ __forceinline__ uint32_t smem_u32(const void* p) {
    uint32_t a;
    asm("{ .reg .u64 t; cvta.to.shared.u64 t, %1; cvt.u32.u64 %0, t; }" : "=r"(a) : "l"(p));
    return a;
}
__device__ __forceinline__ void mbar_init(uint32_t a, uint32_t c) {
    asm volatile("mbarrier.init.shared.b64 [%0], %1;" :: "r"(a), "r"(c) : "memory");
}
__device__ __forceinline__ void mbar_expect_tx(uint32_t a, uint32_t bytes) {
    asm volatile("mbarrier.arrive.expect_tx.shared.b64 _, [%0], %1;" :: "r"(a), "r"(bytes) : "memory");
}
__device__ __forceinline__ void mbar_wait(uint32_t mbar, uint32_t parity) {
    asm volatile(
        "{\n\t.reg .pred P1;\n\t"
        "WL%=:\n\t"
        "mbarrier.try_wait.parity.shared.b64 P1, [%0], %1;\n\t"
        "@!P1 bra WL%=;\n\t}"
        :: "r"(mbar), "r"(parity) : "memory");
}
__device__ __forceinline__ void bulk_cp(uint32_t dst, const void* src, uint32_t bytes, uint32_t mbar) {
    asm volatile(
        "cp.async.bulk.shared::cluster.global.mbarrier::complete_tx::bytes [%0], [%1], %2, [%3];"
        :: "r"(dst), "l"(src), "r"(bytes), "r"(mbar) : "memory");
}
__device__ __forceinline__ void ldsm4(uint32_t& r0, uint32_t& r1, uint32_t& r2, uint32_t& r3, uint32_t addr) {
    asm volatile("ldmatrix.sync.aligned.m8n8.x4.shared.b16 {%0,%1,%2,%3}, [%4];"
        : "=r"(r0), "=r"(r1), "=r"(r2), "=r"(r3) : "r"(addr));
}
__device__ __forceinline__ void ldsm4t(uint32_t& r0, uint32_t& r1, uint32_t& r2, uint32_t& r3, uint32_t addr) {
    asm volatile("ldmatrix.sync.aligned.m8n8.x4.trans.shared.b16 {%0,%1,%2,%3}, [%4];"
        : "=r"(r0), "=r"(r1), "=r"(r2), "=r"(r3) : "r"(addr));
}
__device__ __forceinline__ void ldsm2(uint32_t& r0, uint32_t& r1, uint32_t addr) {
    asm volatile("ldmatrix.sync.aligned.m8n8.x2.shared.b16 {%0,%1}, [%2];"
        : "=r"(r0), "=r"(r1) : "r"(addr));
}
__device__ __forceinline__ void hmma(float* c, const uint32_t* a, const uint32_t* b) {
    asm volatile(
        "mma.sync.aligned.m16n8k16.row.col.f32.f16.f16.f32 "
        "{%0,%1,%2,%3}, {%4,%5,%6,%7}, {%8,%9}, {%0,%1,%2,%3};"
        : "+f"(c[0]), "+f"(c[1]), "+f"(c[2]), "+f"(c[3])
        : "r"(a[0]), "r"(a[1]), "r"(a[2]), "r"(a[3]), "r"(b[0]), "r"(b[1]));
}
__device__ __forceinline__ void tri_decode(int bid, int& lo, int& hi) {
    int r = (int)((sqrtf(8.0f * (float)bid + 1.0f) - 1.0f) * 0.5f);
    while ((r + 1) * (r + 2) / 2 <= bid) ++r;
    while (r * (r + 1) / 2 > bid) --r;
    hi = r;
    lo = bid - r * (r + 1) / 2;
}

// ---------------- kernels ----------------

__global__ void k_feat(const float* __restrict__ x) {
    int n = blockIdx.x * blockDim.x + threadIdx.x;
    if (n >= NPIX) return;
    int y = n / HH, xc = n % HH;
    float f0 = (float)y  * (1.0f / 30.0f);
    float f1 = (float)xc * (1.0f / 30.0f);
    float f2 = x[n]            * 10.0f;
    float f3 = x[NPIX + n]     * 10.0f;
    float f4 = x[2 * NPIX + n] * 10.0f;
    float sq = f0*f0 + f1*f1 + f2*f2 + f3*f3 + f4*f4;
    g_feat[n]            = sq;
    g_feat[NPIX     + n] = f0;
    g_feat[2*NPIX   + n] = f1;
    g_feat[3*NPIX   + n] = f2;
    g_feat[4*NPIX   + n] = f3;
    g_feat[5*NPIX   + n] = f4;
    if (n < HH) g_gauss[n] = expf(-(float)(n * n) * (1.0f / 18.0f));
}

// Upper-tri build into tile-contiguous swizzled layout.
__global__ void __launch_bounds__(256) k_build_t() {
    int ta, tb;
    tri_decode(blockIdx.x, ta, tb);        // ta <= tb
    size_t tbase = (size_t)blockIdx.x * 8192;   // bytes; blockIdx.x == tb*(tb+1)/2+ta
    int tid = threadIdx.x;
    int r  = tid >> 2;
    int cq = (tid & 3) * 16;

    int a = ta * 64 + r;
    float sqa = g_feat[a];
    float a0 = g_feat[NPIX   + a];
    float a1 = g_feat[2*NPIX + a];
    float a2 = g_feat[3*NPIX + a];
    float a3 = g_feat[4*NPIX + a];
    float a4 = g_feat[5*NPIX + a];

    char* Kh = (char*)g_Khi + tbase;
    char* Kl = (char*)g_Klo + tbase;
    #pragma unroll
    for (int q = 0; q < 8; ++q) {
        int col = cq + 2 * q;
        int b = tb * 64 + col;
        float2 sqb = *(const float2*)&g_feat[b];
        float2 b0  = *(const float2*)&g_feat[NPIX   + b];
        float2 b1  = *(const float2*)&g_feat[2*NPIX + b];
        float2 b2  = *(const float2*)&g_feat[3*NPIX + b];
        float2 b3  = *(const float2*)&g_feat[4*NPIX + b];
        float2 b4  = *(const float2*)&g_feat[5*NPIX + b];
        float dotx = a0*b0.x + a1*b1.x + a2*b2.x + a3*b3.x + a4*b4.x;
        float doty = a0*b0.y + a1*b1.y + a2*b2.y + a3*b3.y + a4*b4.y;
        float kx = APP_W * __expf(-0.5f * fmaxf(sqa + sqb.x - 2.0f * dotx, 0.0f));
        float ky = APP_W * __expf(-0.5f * fmaxf(sqa + sqb.y - 2.0f * doty, 0.0f));
        __half hx = __float2half_rn(kx);
        __half hy = __float2half_rn(ky);
        __half lx = __float2half_rn(kx - __half2float(hx));
        __half ly = __float2half_rn(ky - __half2float(hy));
        uint32_t off = SW((uint32_t)(r * 128 + col * 2));
        *(__half2*)(Kh + off) = __halves2half2(hx, hy);
        *(__half2*)(Kl + off) = __halves2half2(lx, ly);
    }
}

__device__ __forceinline__ void write_probs(int n, const float* u, float inv, float* out_cm) {
    int blk = n >> 6, wi = n & 63;
    char* Bh = (char*)g_Bhi + (size_t)blk * 3072;
    char* Bl = (char*)g_Blo + (size_t)blk * 3072;
    #pragma unroll
    for (int c = 0; c < CC; c++) {
        float o = u[c] * inv;
        out_cm[c * NPIX + n] = o;
        __half h = __float2half_rn(o);
        uint32_t off = SW((uint32_t)(c * 128 + wi * 2));
        *(__half*)(Bh + off) = h;
        *(__half*)(Bl + off) = __float2half_rn(o - __half2float(h));
    }
}

__global__ void k_init(const float* __restrict__ yhat, float* __restrict__ out_cm) {
    int n = blockIdx.x * blockDim.x + threadIdx.x;
    if (n >= NPIX) return;
    float u[CC];
    float mx = -1e30f;
    #pragma unroll
    for (int c = 0; c < CC; c++) {
        float v = yhat[c * NPIX + n];
        g_unary[c * NPIX + n] = v;
        u[c] = v;
        mx = fmaxf(mx, v);
    }
    float s = 0.0f;
    #pragma unroll
    for (int c = 0; c < CC; c++) { u[c] = __expf(u[c] - mx); s += u[c]; }
    write_probs(n, u, 1.0f / s, out_cm);
    // zero padded classes (stay zero all run)
    int blk = n >> 6, wi = n & 63;
    char* Bh = (char*)g_Bhi + (size_t)blk * 3072;
    char* Bl = (char*)g_Blo + (size_t)blk * 3072;
    #pragma unroll
    for (int c = CC; c < NB; c++) {
        uint32_t off = SW((uint32_t)(c * 128 + wi * 2));
        *(__half*)(Bh + off) = __float2half_rn(0.0f);
        *(__half*)(Bl + off) = __float2half_rn(0.0f);
    }
}

// thread-0 stage fill: 8 large bulk copies
__device__ __forceinline__ void fill_stage(uint32_t st, int I, int J0, uint32_t mb) {
    #pragma unroll
    for (int k = 0; k < 2; ++k) {
        int J = (k == 0) ? J0 : ((J0 + 1 == NBLK) ? 0 : J0 + 1);
        int lo = (I < J) ? I : J;
        int hi = (I < J) ? J : I;
        size_t tb2 = (size_t)(hi * (hi + 1) / 2 + lo) * 8192;
        bulk_cp(st + A0HI + k * 16384, (char*)g_Khi + tb2, 8192, mb);
        bulk_cp(st + A0LO + k * 16384, (char*)g_Klo + tb2, 8192, mb);
        bulk_cp(st + P0HI + k * 6144, (char*)g_Bhi + (size_t)J * 3072, 3072, mb);
        bulk_cp(st + P0LO + k * 6144, (char*)g_Blo + (size_t)J * 3072, 3072, mb);
    }
}

// Owner-computes symmetric GEMM, 2 J-blocks per stage, paired L2 schedule.
__global__ void __launch_bounds__(256, 2) k_gemm_sym3() {
    extern __shared__ char smem[];
    __shared__ uint64_t mbar_s[NSTAGE];
    uint32_t sb = smem_u32(smem);
    int tid = threadIdx.x;
    int lane = tid & 31;
    int w = tid >> 5;
    int r = w & 3;           // 16-row group
    int kh = w >> 2;         // k-half
    int I = blockIdx.x;
    int h = blockIdx.y;

    uint32_t mb[NSTAGE];
    #pragma unroll
    for (int s = 0; s < NSTAGE; s++) mb[s] = smem_u32(&mbar_s[s]);
    if (tid < NSTAGE) mbar_init(mb[tid], 1);
    __syncthreads();
    if (tid == 0) {
        #pragma unroll
        for (int s = 0; s < NSTAGE; s++) {
            mbar_expect_tx(mb[s], FULLB);
            int J0 = (72 * h + 2 * s - I + 2 * NBLK) % NBLK;
            fill_stage(sb + s * STAGEB, I, J0, mb[s]);
        }
    }

    // --- precomputed swizzled frag offsets (relative to region bases) ---
    int arow = r * 16 + (lane & 15);
    int ach = (lane >> 4) + kh * 4;
    uint32_t a_sw[2];
    #pragma unroll
    for (int ks = 0; ks < 2; ks++)
        a_sw[ks] = (uint32_t)(arow * 128 + (((ach + ks * 2) ^ (arow & 7)) << 4));
    int gg = lane >> 3;
    int tch = r * 2 + (gg & 1);
    int trow = kh * 32 + (gg >> 1) * 8 + (lane & 7);
    uint32_t t_sw[2];
    #pragma unroll
    for (int ks = 0; ks < 2; ks++)
        t_sw[ks] = (uint32_t)((trow + ks * 16) * 128 + ((tch ^ (lane & 7)) << 4));
    int l2 = lane & 15;
    int brl = l2 & 7;
    int bch = ((l2 >> 3) & 1) + kh * 4;
    uint32_t b_sw[3][2];
    #pragma unroll
    for (int nt = 0; nt < 3; nt++)
        #pragma unroll
        for (int ks = 0; ks < 2; ks++)
            b_sw[nt][ks] = (uint32_t)((nt * 8 + brl) * 128 + (((bch + ks * 2) ^ brl) << 4));

    float acc[3][3][4];
    #pragma unroll
    for (int tm = 0; tm < 3; tm++)
        #pragma unroll
        for (int nt = 0; nt < 3; nt++)
            #pragma unroll
            for (int q = 0; q < 4; q++) acc[tm][nt][q] = 0.0f;

    int Jbase = (72 * h - I + 2 * NBLK) % NBLK;   // J at u=0

    for (int t = 0; t < NSTEP; ++t) {
        int s = t & 1;
        uint32_t st = sb + s * STAGEB;
        mbar_wait(mb[s], (t >> 1) & 1);

        #pragma unroll
        for (int k = 0; k < 2; ++k) {
            int u = 2 * t + k;
            int J = Jbase + u; if (J >= NBLK) J -= NBLK;
            uint32_t Ah = st + A0HI + k * 16384;
            uint32_t Al = st + A0LO + k * 16384;
            uint32_t Ph = st + P0HI + k * 6144;
            uint32_t Pl = st + P0LO + k * 6144;
            if (J >= I) {
                #pragma unroll
                for (int ks = 0; ks < 2; ++ks) {
                    uint32_t ah[4], al[4];
                    ldsm4(ah[0], ah[1], ah[2], ah[3], Ah + a_sw[ks]);
                    ldsm4(al[0], al[1], al[2], al[3], Al + a_sw[ks]);
                    #pragma unroll
                    for (int nt = 0; nt < 3; ++nt) {
                        uint32_t bh[2], bl[2];
                        ldsm2(bh[0], bh[1], Ph + b_sw[nt][ks]);
                        ldsm2(bl[0], bl[1], Pl + b_sw[nt][ks]);
                        hmma(acc[0][nt], ah, bh);
                        hmma(acc[1][nt], ah, bl);
                        hmma(acc[2][nt], al, bh);
                    }
                }
            } else {
                #pragma unroll
                for (int ks = 0; ks < 2; ++ks) {
                    uint32_t ah[4], al[4];
                    ldsm4t(ah[0], ah[1], ah[2], ah[3], Ah + t_sw[ks]);
                    ldsm4t(al[0], al[1], al[2], al[3], Al + t_sw[ks]);
                    #pragma unroll
                    for (int nt = 0; nt < 3; ++nt) {
                        uint32_t bh[2], bl[2];
                        ldsm2(bh[0], bh[1], Ph + b_sw[nt][ks]);
                        ldsm2(bl[0], bl[1], Pl + b_sw[nt][ks]);
                        hmma(acc[0][nt], ah, bh);
                        hmma(acc[1][nt], ah, bl);
                        hmma(acc[2][nt], al, bh);
                    }
                }
            }
        }
        __syncthreads();
        if (t + NSTAGE < NSTEP && tid == 0) {
            mbar_expect_tx(mb[s], FULLB);
            int J0 = Jbase + 2 * (t + NSTAGE); if (J0 >= NBLK) J0 -= NBLK;
            fill_stage(st, I, J0, mb[s]);
        }
    }

    // epilogue: 3-term sum, k-half reduction via smem, single STG
    float sum_[3][4];
    #pragma unroll
    for (int nt = 0; nt < 3; nt++)
        #pragma unroll
        for (int q = 0; q < 4; q++)
            sum_[nt][q] = acc[0][nt][q] + acc[1][nt][q] + acc[2][nt][q];

    float* red = (float*)smem;
    int row16 = lane >> 2;
    int cb = (lane & 3) * 2;
    if (kh == 1) {
        #pragma unroll
        for (int nt = 0; nt < 3; ++nt) {
            red[(r * 16 + row16) * 26 + nt * 8 + cb]         = sum_[nt][0];
            red[(r * 16 + row16) * 26 + nt * 8 + cb + 1]     = sum_[nt][1];
            red[(r * 16 + row16 + 8) * 26 + nt * 8 + cb]     = sum_[nt][2];
            red[(r * 16 + row16 + 8) * 26 + nt * 8 + cb + 1] = sum_[nt][3];
        }
    }
    __syncthreads();
    if (kh == 0) {
        float* dst = g_part[h];
        int rg0 = I * 64 + r * 16 + row16;
        #pragma unroll
        for (int nt = 0; nt < 3; ++nt) {
            float s0 = sum_[nt][0] + red[(r * 16 + row16) * 26 + nt * 8 + cb];
            float s1 = sum_[nt][1] + red[(r * 16 + row16) * 26 + nt * 8 + cb + 1];
            float s2 = sum_[nt][2] + red[(r * 16 + row16 + 8) * 26 + nt * 8 + cb];
            float s3 = sum_[nt][3] + red[(r * 16 + row16 + 8) * 26 + nt * 8 + cb + 1];
            *(float2*)&dst[(size_t)rg0 * NB + nt * 8 + cb]       = make_float2(s0, s1);
            *(float2*)&dst[(size_t)(rg0 + 8) * NB + nt * 8 + cb] = make_float2(s2, s3);
        }
    }
}

// Separable smoothness: horizontal pass.
__global__ void k_convx(const float* __restrict__ out_cm) {
    __shared__ float sg[HH];
    if (threadIdx.x < HH) sg[threadIdx.x] = g_gauss[threadIdx.x];
    __syncthreads();
    int idx = blockIdx.x * blockDim.x + threadIdx.x;
    if (idx >= CC * NPIX) return;
    int xp = idx % HH;
    const float* row = out_cm + (idx - xp);
    float s = 0.0f;
    #pragma unroll 8
    for (int xx = 0; xx < HH; ++xx) {
        int d = xx - xp; d = (d < 0) ? -d : d;
        s += row[xx] * sg[d];
    }
    g_tmp[idx] = s;
}

// Separable smoothness: vertical pass.
__global__ void k_convy() {
    __shared__ float sg[HH];
    if (threadIdx.x < HH) sg[threadIdx.x] = g_gauss[threadIdx.x];
    __syncthreads();
    int idx = blockIdx.x * blockDim.x + threadIdx.x;
    if (idx >= CC * NPIX) return;
    int xp = idx % HH;
    int yp = (idx / HH) % HH;
    int c  = idx / NPIX;
    const float* col = g_tmp + c * NPIX + xp;
    float s = 0.0f;
    #pragma unroll 8
    for (int y = 0; y < HH; ++y) {
        int d = y - yp; d = (d < 0) ? -d : d;
        s += col[y * HH] * sg[d];
    }
    g_smo[idx] = s;
}

__global__ void k_combine(const float* __restrict__ mu, float* __restrict__ out_cm) {
    __shared__ float smu[CC * CC];
    for (int i = threadIdx.x; i < CC * CC; i += blockDim.x) smu[i] = mu[i];
    __syncthreads();
    int n = blockIdx.x * blockDim.x + threadIdx.x;
    if (n >= NPIX) return;
    float m[CC];
    #pragma unroll
    for (int c = 0; c < CC; c++)
        m[c] = g_part[0][(size_t)n * NB + c] + g_part[1][(size_t)n * NB + c]
             + SMO_W * g_smo[c * NPIX + n];
    float u[CC];
    float mx = -1e30f;
    #pragma unroll
    for (int c = 0; c < CC; c++) {
        float s = 0.0f;
        #pragma unroll
        for (int c2 = 0; c2 < CC; c2++) s = fmaf(smu[c2 * CC + c], m[c2], s);
        float v = g_unary[c * NPIX + n] + s;
        g_unary[c * NPIX + n] = v;
        u[c] = v;
        mx = fmaxf(mx, v);
    }
    float s = 0.0f;
    #pragma unroll
    for (int c = 0; c < CC; c++) { u[c] = __expf(u[c] - mx); s += u[c]; }
    write_probs(n, u, 1.0f / s, out_cm);
}

// ---------------- launch ----------------
extern "C" void kernel_launch(void* const* d_in, const int* in_sizes, int n_in,
                              void* d_out, int out_size) {
    const float* x    = (const float*)d_in[0];
    const float* yhat = (const float*)d_in[1];
    const float* mu   = (const float*)d_in[2];
    float* out = (float*)d_out;

    cudaFuncSetAttribute(k_gemm_sym3, cudaFuncAttributeMaxDynamicSharedMemorySize, GEMM_SMEM);

    k_feat<<<(NPIX + 255) / 256, 256>>>(x);
    k_build_t<<<NTILE, 256>>>();
    k_init<<<(NPIX + 255) / 256, 256>>>(yhat, out);

    for (int it = 0; it < CRF_ITERS; ++it) {
        k_gemm_sym3<<<dim3(NBLK, 2), 256, GEMM_SMEM>>>();
        k_convx<<<(CC * NPIX + 127) / 128, 128>>>(out);
        k_convy<<<(CC * NPIX + 127) / 128, 128>>>();
        k_combine<<<(NPIX + 127) / 128, 128>>>(mu, out);
    }
}